// round 1
// baseline (speedup 1.0000x reference)
#include <cuda_runtime.h>
#include <math_constants.h>
#include <cstdint>

// JAX >= 0.4.36 defaults jax_threefry_partitionable=True. If rel_err explodes
// (~0.9), flip this to 0 (legacy split/bit-gen path).
#define JAX_PARTITIONABLE 1

constexpr int B = 4, L = 2048, H = 8, D = 64, S = 2048;
constexpr int U = 40, NTOP = 40, BH = B * H;

__device__ int   g_idx[L * U];
__device__ float g_M[BH * L];
__device__ int   g_top[BH * NTOP];
__device__ float g_sumV[BH * D];

// ---------------------------------------------------------------------------
// threefry2x32 (matches jax/_src/prng.py reference implementation)
// ---------------------------------------------------------------------------
__device__ __forceinline__ uint2 threefry2x32(uint32_t k0, uint32_t k1,
                                              uint32_t x0, uint32_t x1) {
    uint32_t ks2 = k0 ^ k1 ^ 0x1BD11BDAu;
    x0 += k0; x1 += k1;
#define TF_RND(r) { x0 += x1; x1 = (x1 << (r)) | (x1 >> (32 - (r))); x1 ^= x0; }
    TF_RND(13) TF_RND(15) TF_RND(26) TF_RND(6)
    x0 += k1;  x1 += ks2 + 1u;
    TF_RND(17) TF_RND(29) TF_RND(16) TF_RND(24)
    x0 += ks2; x1 += k0 + 2u;
    TF_RND(13) TF_RND(15) TF_RND(26) TF_RND(6)
    x0 += k0;  x1 += k1 + 3u;
    TF_RND(17) TF_RND(29) TF_RND(16) TF_RND(24)
    x0 += k1;  x1 += ks2 + 4u;
    TF_RND(13) TF_RND(15) TF_RND(26) TF_RND(6)
    x0 += ks2; x1 += k0 + 5u;
#undef TF_RND
    return make_uint2(x0, x1);
}

// idx_sample = randint(key(42), (L,U), 0, 2048). span=2048 is a power of two so
// the jax randint reduces to lower_bits & 2047 where lower_bits = random_bits(k2).
__global__ void gen_idx_kernel() {
    int i = blockIdx.x * blockDim.x + threadIdx.x;
    if (i >= L * U) return;
    uint32_t bits;
#if JAX_PARTITIONABLE
    // fold-like split: k2 = threefry(key, (0, 1)); bits_i = o0 ^ o1 of threefry(k2,(0,i))
    uint2 k2 = threefry2x32(0u, 42u, 0u, 1u);
    uint2 r  = threefry2x32(k2.x, k2.y, 0u, (uint32_t)i);
    bits = r.x ^ r.y;
#else
    // legacy split: counts = iota(4): blocks (0,2),(1,3); k2 = (o1_b0, o1_b1)
    uint2 a = threefry2x32(0u, 42u, 0u, 2u);
    uint2 b = threefry2x32(0u, 42u, 1u, 3u);
    uint32_t k20 = a.y, k21 = b.y;
    const uint32_t half = (uint32_t)(L * U) / 2u;
    if ((uint32_t)i < half) {
        uint2 r = threefry2x32(k20, k21, (uint32_t)i, (uint32_t)i + half);
        bits = r.x;
    } else {
        uint2 r = threefry2x32(k20, k21, (uint32_t)i - half, (uint32_t)i);
        bits = r.y;
    }
#endif
    g_idx[i] = (int)(bits & (uint32_t)(S - 1));
}

// ---------------------------------------------------------------------------
// M[b,h,l] = max_j(Q_l . K_idx[l,j]) - (sum_j Q_l . K_idx[l,j]) / S   (fp32!)
// One warp per (bh, l) row. Lane holds Q[lane], Q[lane+32].
// ---------------------------------------------------------------------------
__global__ void compute_M_kernel(const float* __restrict__ Q,
                                 const float* __restrict__ K) {
    int warp = (blockIdx.x * blockDim.x + threadIdx.x) >> 5;
    int lane = threadIdx.x & 31;
    if (warp >= BH * L) return;
    int l  = warp & (L - 1);
    int bh = warp >> 11;

    const float* qrow = Q + (size_t)warp * D;
    float q0 = qrow[lane], q1 = qrow[lane + 32];
    const float* Kb = K + (size_t)bh * S * D;

    float mx = -CUDART_INF_F, sm = 0.f;
#pragma unroll 4
    for (int j = 0; j < U; j++) {
        int kidx = g_idx[l * U + j];
        const float* krow = Kb + (size_t)kidx * D;
        float p = fmaf(q0, krow[lane], q1 * krow[lane + 32]);
#pragma unroll
        for (int o = 16; o; o >>= 1) p += __shfl_xor_sync(0xffffffffu, p, o);
        mx = fmaxf(mx, p);
        sm += p;
    }
    if (lane == 0) g_M[warp] = mx - sm * (1.0f / (float)S);
}

// ---------------------------------------------------------------------------
// top-40 per (bh). Iterative argmax with lax.top_k tie-break (smallest index).
// ---------------------------------------------------------------------------
__global__ void topk_kernel() {
    int bh  = blockIdx.x;
    int tid = threadIdx.x;
    __shared__ float vals[L];
    __shared__ float wv[8];
    __shared__ int   wi[8];
    for (int i = tid; i < L; i += 256) vals[i] = g_M[bh * L + i];
    __syncthreads();
    for (int it = 0; it < NTOP; it++) {
        float best = -CUDART_INF_F; int bi = L;
        for (int i = tid; i < L; i += 256) {
            float v = vals[i];
            if (v > best || (v == best && i < bi)) { best = v; bi = i; }
        }
#pragma unroll
        for (int o = 16; o; o >>= 1) {
            float ov = __shfl_xor_sync(0xffffffffu, best, o);
            int   oi = __shfl_xor_sync(0xffffffffu, bi, o);
            if (ov > best || (ov == best && oi < bi)) { best = ov; bi = oi; }
        }
        if ((tid & 31) == 0) { wv[tid >> 5] = best; wi[tid >> 5] = bi; }
        __syncthreads();
        if (tid == 0) {
            float fb = wv[0]; int fi = wi[0];
            for (int w = 1; w < 8; w++)
                if (wv[w] > fb || (wv[w] == fb && wi[w] < fi)) { fb = wv[w]; fi = wi[w]; }
            g_top[bh * NTOP + it] = fi;
            vals[fi] = -CUDART_INF_F;
        }
        __syncthreads();
    }
}

// ---------------------------------------------------------------------------
// sumV[bh][d] = sum_s V[bh,s,d]
// ---------------------------------------------------------------------------
__global__ void sumv_kernel(const float* __restrict__ V) {
    int bh = blockIdx.x;
    int tid = threadIdx.x;
    int d = tid & 63, g = tid >> 6;  // 4 groups x 64 dims
    const float* vb = V + (size_t)bh * S * D;
    float acc = 0.f;
    for (int s = g; s < S; s += 4) acc += vb[(size_t)s * D + d];
    __shared__ float red[4][64];
    red[g][d] = acc;
    __syncthreads();
    if (g == 0) g_sumV[bh * D + d] = red[0][d] + red[1][d] + red[2][d] + red[3][d];
}

// ---------------------------------------------------------------------------
// out[bh,l,d] = sumV[bh][d] for every row (top rows overwritten later)
// ---------------------------------------------------------------------------
__global__ void fill_kernel(float* __restrict__ out) {
    int i = blockIdx.x * blockDim.x + threadIdx.x;  // B*H*L*D
    int d = i & 63;
    int bh = i >> 17;  // L*D = 131072 = 2^17
    out[i] = g_sumV[bh * D + d];
}

// ---------------------------------------------------------------------------
// Attention for the 40 top rows per (bh). Block = 8 queries (warp per query),
// online softmax over S in 64-key tiles held in padded smem.
// ---------------------------------------------------------------------------
__global__ void attn_kernel(const float* __restrict__ Q,
                            const float* __restrict__ K,
                            const float* __restrict__ V,
                            float* __restrict__ out) {
    int bh    = blockIdx.x / 5;
    int chunk = blockIdx.x % 5;
    int tid = threadIdx.x, w = tid >> 5, lane = tid & 31;

    __shared__ float Qs[8][64];
    __shared__ float Ks[64][65];
    __shared__ float Vs[64][65];
    __shared__ float Ps[8][64];

    int qi   = chunk * 8 + w;           // 0..39
    int qrow = g_top[bh * NTOP + qi];   // broadcast load
    const float* qsrc = Q + ((size_t)bh * L + qrow) * D;
    Qs[w][lane]      = qsrc[lane];
    Qs[w][lane + 32] = qsrc[lane + 32];
    __syncwarp();

    const float* Kb = K + (size_t)bh * S * D;
    const float* Vb = V + (size_t)bh * S * D;

    float m = -CUDART_INF_F, lsum = 0.f, acc0 = 0.f, acc1 = 0.f;

    for (int t = 0; t < S / 64; t++) {
        __syncthreads();
        for (int i = tid; i < 64 * 64; i += 256) {
            int s = i >> 6, d = i & 63;
            Ks[s][d] = Kb[(size_t)(t * 64 + s) * D + d];
            Vs[s][d] = Vb[(size_t)(t * 64 + s) * D + d];
        }
        __syncthreads();

        float s0 = 0.f, s1 = 0.f;
#pragma unroll
        for (int d = 0; d < 64; d++) {
            float qd = Qs[w][d];
            s0 = fmaf(qd, Ks[lane][d], s0);
            s1 = fmaf(qd, Ks[lane + 32][d], s1);
        }
        s0 *= 0.125f; s1 *= 0.125f;

        float tm = fmaxf(s0, s1);
#pragma unroll
        for (int o = 16; o; o >>= 1) tm = fmaxf(tm, __shfl_xor_sync(0xffffffffu, tm, o));
        float mnew = fmaxf(m, tm);
        float corr = expf(m - mnew);      // 0 on first tile (-inf - finite)
        float p0 = expf(s0 - mnew);
        float p1 = expf(s1 - mnew);
        float ts = p0 + p1;
#pragma unroll
        for (int o = 16; o; o >>= 1) ts += __shfl_xor_sync(0xffffffffu, ts, o);
        lsum = lsum * corr + ts;
        acc0 *= corr; acc1 *= corr;
        m = mnew;

        Ps[w][lane] = p0; Ps[w][lane + 32] = p1;
        __syncwarp();
#pragma unroll
        for (int s = 0; s < 64; s++) {
            float p = Ps[w][s];
            acc0 = fmaf(p, Vs[s][lane], acc0);
            acc1 = fmaf(p, Vs[s][lane + 32], acc1);
        }
    }

    float inv = 1.0f / lsum;
    size_t orow = ((size_t)bh * L + qrow) * D;
    out[orow + lane]      = acc0 * inv;
    out[orow + lane + 32] = acc1 * inv;
}

// ---------------------------------------------------------------------------
extern "C" void kernel_launch(void* const* d_in, const int* in_sizes, int n_in,
                              void* d_out, int out_size) {
    const float* q = (const float*)d_in[0];
    const float* k = (const float*)d_in[1];
    const float* v = (const float*)d_in[2];
    float* out = (float*)d_out;

    gen_idx_kernel<<<(L * U + 255) / 256, 256>>>();
    compute_M_kernel<<<(BH * L) / 8, 256>>>(q, k);
    topk_kernel<<<BH, 256>>>();
    sumv_kernel<<<BH, 256>>>(v);
    fill_kernel<<<(B * H * L * D) / 256, 256>>>(out);
    attn_kernel<<<BH * 5, 256>>>(q, k, v, out);
}

// round 2
// speedup vs baseline: 1.2926x; 1.2926x over previous
#include <cuda_runtime.h>
#include <math_constants.h>
#include <cstdint>

#define JAX_PARTITIONABLE 1

constexpr int B = 4, L = 2048, H = 8, D = 64, S = 2048;
constexpr int U = 40, NTOP = 40, BH = B * H;

__device__ int   g_idx[L * U];
__device__ float g_M[BH * L];
__device__ int   g_top[BH * NTOP];
__device__ float g_sumV[BH * D];
__device__ float g_part[BH * 8 * D];

// ---------------------------------------------------------------------------
// threefry2x32 (matches jax/_src/prng.py)
// ---------------------------------------------------------------------------
__device__ __forceinline__ uint2 threefry2x32(uint32_t k0, uint32_t k1,
                                              uint32_t x0, uint32_t x1) {
    uint32_t ks2 = k0 ^ k1 ^ 0x1BD11BDAu;
    x0 += k0; x1 += k1;
#define TF_RND(r) { x0 += x1; x1 = (x1 << (r)) | (x1 >> (32 - (r))); x1 ^= x0; }
    TF_RND(13) TF_RND(15) TF_RND(26) TF_RND(6)
    x0 += k1;  x1 += ks2 + 1u;
    TF_RND(17) TF_RND(29) TF_RND(16) TF_RND(24)
    x0 += ks2; x1 += k0 + 2u;
    TF_RND(13) TF_RND(15) TF_RND(26) TF_RND(6)
    x0 += k0;  x1 += k1 + 3u;
    TF_RND(17) TF_RND(29) TF_RND(16) TF_RND(24)
    x0 += k1;  x1 += ks2 + 4u;
    TF_RND(13) TF_RND(15) TF_RND(26) TF_RND(6)
    x0 += ks2; x1 += k0 + 5u;
#undef TF_RND
    return make_uint2(x0, x1);
}

__global__ void gen_idx_kernel() {
    int i = blockIdx.x * blockDim.x + threadIdx.x;
    if (i >= L * U) return;
    uint32_t bits;
#if JAX_PARTITIONABLE
    uint2 k2 = threefry2x32(0u, 42u, 0u, 1u);
    uint2 r  = threefry2x32(k2.x, k2.y, 0u, (uint32_t)i);
    bits = r.x ^ r.y;
#else
    uint2 a = threefry2x32(0u, 42u, 0u, 2u);
    uint2 b = threefry2x32(0u, 42u, 1u, 3u);
    uint32_t k20 = a.y, k21 = b.y;
    const uint32_t half = (uint32_t)(L * U) / 2u;
    if ((uint32_t)i < half) {
        uint2 r = threefry2x32(k20, k21, (uint32_t)i, (uint32_t)i + half);
        bits = r.x;
    } else {
        uint2 r = threefry2x32(k20, k21, (uint32_t)i - half, (uint32_t)i);
        bits = r.y;
    }
#endif
    g_idx[i] = (int)(bits & (uint32_t)(S - 1));
}

// ---------------------------------------------------------------------------
// M: half-warp per sample, float4 loads. Block = 8 warps = 16 l-rows.
// grid = BH * L/16 = 4096 blocks.
// ---------------------------------------------------------------------------
__global__ void compute_M_kernel(const float* __restrict__ Q,
                                 const float* __restrict__ K) {
    int tid = threadIdx.x;
    int bh = blockIdx.x >> 7;                 // 128 blocks per bh
    int block_l = (blockIdx.x & 127) * 16;

    __shared__ int sidx[16 * U];
    for (int i = tid; i < 16 * U; i += 256) sidx[i] = g_idx[block_l * U + i];
    __syncthreads();

    int warp = tid >> 5, lane = tid & 31;
    int half = lane >> 4, lid = lane & 15;
    int lrow = warp * 2 + half;               // 0..15
    int l = block_l + lrow;

    const float4* Kb4 = (const float4*)(K + (size_t)bh * S * D);
    const float4* q4  = (const float4*)(Q + ((size_t)bh * L + l) * D);
    float4 q = q4[lid];

    float mx = -CUDART_INF_F, sm = 0.f;
#pragma unroll 8
    for (int j = 0; j < U; j++) {
        int kidx = sidx[lrow * U + j];
        float4 k = Kb4[kidx * 16 + lid];
        float p = q.x * k.x + q.y * k.y + q.z * k.z + q.w * k.w;
#pragma unroll
        for (int o = 8; o; o >>= 1) p += __shfl_xor_sync(0xffffffffu, p, o);
        mx = fmaxf(mx, p);
        sm += p;
    }
    if (lid == 0) g_M[bh * L + l] = mx - sm * (1.0f / (float)S);
}

// ---------------------------------------------------------------------------
// Exact top-40 per (bh) via 4-pass radix select on monotone-mapped keys.
// g_top receives the SET of top indices (order irrelevant downstream).
// ---------------------------------------------------------------------------
__global__ void topk_kernel() {
    int bh = blockIdx.x, tid = threadIdx.x;       // 256 threads
    int warp = tid >> 5;
    __shared__ uint32_t keys[L];
    __shared__ int hist[8][256];
    __shared__ int fin[256];
    __shared__ uint32_t sh_prefix;
    __shared__ int sh_need, sh_cnt;

    for (int i = tid; i < L; i += 256) {
        uint32_t b = __float_as_uint(g_M[bh * L + i]);
        keys[i] = (b & 0x80000000u) ? ~b : (b | 0x80000000u);
    }
    if (tid == 0) { sh_prefix = 0u; sh_need = NTOP; sh_cnt = 0; }
    __syncthreads();

    for (int shift = 24; shift >= 0; shift -= 8) {
        for (int i = tid; i < 8 * 256; i += 256) ((int*)hist)[i] = 0;
        __syncthreads();
        uint32_t prefix = sh_prefix;
        uint32_t maskhi = (shift == 24) ? 0u : (0xFFFFFFFFu << (shift + 8));
        for (int i = tid; i < L; i += 256) {
            uint32_t k = keys[i];
            if ((k & maskhi) == prefix)
                atomicAdd(&hist[warp][(k >> shift) & 255], 1);
        }
        __syncthreads();
        for (int i = tid; i < 256; i += 256) {
            int s = 0;
#pragma unroll
            for (int w = 0; w < 8; w++) s += hist[w][i];
            fin[i] = s;
        }
        __syncthreads();
        if (tid == 0) {
            int need = sh_need, cum = 0, d;
            for (d = 255; d >= 0; d--) {
                int c = fin[d];
                if (cum + c >= need) { sh_need = need - cum; break; }
                cum += c;
            }
            sh_prefix = prefix | ((uint32_t)d << shift);
        }
        __syncthreads();
    }
    uint32_t T = sh_prefix;
    int take_eq = sh_need;
    for (int i = tid; i < L; i += 256) {
        uint32_t k = keys[i];
        if (k > T) {
            int p = atomicAdd(&sh_cnt, 1);
            g_top[bh * NTOP + p] = i;
        } else if (k == T) {
            int r = 0;
            for (int j = 0; j < i; j++) if (keys[j] == T) r++;
            if (r < take_eq) {
                int p = atomicAdd(&sh_cnt, 1);
                g_top[bh * NTOP + p] = i;
            }
        }
    }
}

// ---------------------------------------------------------------------------
// sumV partials: grid = BH*8, each block sums 256 rows.
// ---------------------------------------------------------------------------
__global__ void sumv_part_kernel(const float* __restrict__ V) {
    int blk = blockIdx.x;
    int bh = blk >> 3, p = blk & 7;
    int tid = threadIdx.x;
    int d = tid & 63, g = tid >> 6;               // 4 groups x 64 dims
    const float* vb = V + (size_t)bh * S * D + (size_t)(p * 256) * D;
    float acc = 0.f;
#pragma unroll 4
    for (int s = g; s < 256; s += 4) acc += vb[(size_t)s * D + d];
    __shared__ float red[4][64];
    red[g][d] = acc;
    __syncthreads();
    if (g == 0)
        g_part[(bh * 8 + p) * D + d] = red[0][d] + red[1][d] + red[2][d] + red[3][d];
}

__global__ void sumv_reduce_kernel() {
    int bh = blockIdx.x, d = threadIdx.x;
    float s = 0.f;
#pragma unroll
    for (int p = 0; p < 8; p++) s += g_part[(bh * 8 + p) * D + d];
    g_sumV[bh * D + d] = s;
}

// ---------------------------------------------------------------------------
// fill: float4 stores of the broadcast row sum.
// ---------------------------------------------------------------------------
__global__ void fill_kernel(float4* __restrict__ out) {
    int i = blockIdx.x * blockDim.x + threadIdx.x;   // B*H*L*D/4 = 1M
    int d4 = i & 15;
    int bh = i >> 15;                                // L*D/4 = 32768
    out[i] = ((const float4*)g_sumV)[bh * 16 + d4];
}

// ---------------------------------------------------------------------------
// Attention: 4 warps/block, 2 queries/warp, 8 queries/block, 5 blocks/bh.
// ---------------------------------------------------------------------------
__global__ void attn_kernel(const float* __restrict__ Q,
                            const float* __restrict__ K,
                            const float* __restrict__ V,
                            float* __restrict__ out) {
    int bh    = blockIdx.x / 5;
    int chunk = blockIdx.x % 5;
    int tid = threadIdx.x, w = tid >> 5, lane = tid & 31;

    __shared__ float4 Ks4[64][17];     // 64 rows x 68 floats (padded)
    __shared__ float4 Vs4[64][17];
    __shared__ float  Qs[8][64];
    __shared__ float  Ps[8][64];

    // load 8 queries (gathered rows)
    for (int i = tid; i < 8 * 64; i += 128) {
        int q = i >> 6, d = i & 63;
        int qrow = g_top[bh * NTOP + chunk * 8 + q];
        Qs[q][d] = Q[((size_t)bh * L + qrow) * D + d];
    }
    __syncthreads();

    const float4* Kb4 = (const float4*)(K + (size_t)bh * S * D);
    const float4* Vb4 = (const float4*)(V + (size_t)bh * S * D);
    const float* Vsf = (const float*)Vs4;

    int qa = 2 * w, qb = 2 * w + 1;
    float mA = -CUDART_INF_F, mB = -CUDART_INF_F;
    float lA = 0.f, lB = 0.f;
    float accA0 = 0.f, accA1 = 0.f, accB0 = 0.f, accB1 = 0.f;

    for (int t = 0; t < S / 64; t++) {
        __syncthreads();
        for (int i = tid; i < 1024; i += 128) {
            int s = i >> 4, c = i & 15;
            Ks4[s][c] = Kb4[(size_t)(t * 64 + s) * 16 + c];
            Vs4[s][c] = Vb4[(size_t)(t * 64 + s) * 16 + c];
        }
        __syncthreads();

        // QK: scores for keys (lane, lane+32), 2 queries
        float sA0 = 0.f, sA1 = 0.f, sB0 = 0.f, sB1 = 0.f;
#pragma unroll
        for (int d4 = 0; d4 < 16; d4++) {
            float4 k0 = Ks4[lane][d4];
            float4 k1 = Ks4[lane + 32][d4];
            float4 a = ((const float4*)Qs[qa])[d4];
            float4 b = ((const float4*)Qs[qb])[d4];
            sA0 += a.x * k0.x + a.y * k0.y + a.z * k0.z + a.w * k0.w;
            sA1 += a.x * k1.x + a.y * k1.y + a.z * k1.z + a.w * k1.w;
            sB0 += b.x * k0.x + b.y * k0.y + b.z * k0.z + b.w * k0.w;
            sB1 += b.x * k1.x + b.y * k1.y + b.z * k1.z + b.w * k1.w;
        }
        sA0 *= 0.125f; sA1 *= 0.125f; sB0 *= 0.125f; sB1 *= 0.125f;

        // online softmax (both queries)
        float tmA = fmaxf(sA0, sA1), tmB = fmaxf(sB0, sB1);
#pragma unroll
        for (int o = 16; o; o >>= 1) {
            tmA = fmaxf(tmA, __shfl_xor_sync(0xffffffffu, tmA, o));
            tmB = fmaxf(tmB, __shfl_xor_sync(0xffffffffu, tmB, o));
        }
        float mnA = fmaxf(mA, tmA), mnB = fmaxf(mB, tmB);
        float cA = __expf(mA - mnA), cB = __expf(mB - mnB);
        float pA0 = __expf(sA0 - mnA), pA1 = __expf(sA1 - mnA);
        float pB0 = __expf(sB0 - mnB), pB1 = __expf(sB1 - mnB);
        float tsA = pA0 + pA1, tsB = pB0 + pB1;
#pragma unroll
        for (int o = 16; o; o >>= 1) {
            tsA += __shfl_xor_sync(0xffffffffu, tsA, o);
            tsB += __shfl_xor_sync(0xffffffffu, tsB, o);
        }
        lA = lA * cA + tsA;  lB = lB * cB + tsB;
        accA0 *= cA; accA1 *= cA; accB0 *= cB; accB1 *= cB;
        mA = mnA; mB = mnB;

        Ps[qa][lane] = pA0; Ps[qa][lane + 32] = pA1;
        Ps[qb][lane] = pB0; Ps[qb][lane + 32] = pB1;
        __syncwarp();

        // PV: V rows shared between the 2 queries
#pragma unroll
        for (int s4 = 0; s4 < 16; s4++) {
            float4 pa = ((const float4*)Ps[qa])[s4];
            float4 pb = ((const float4*)Ps[qb])[s4];
            float v00 = Vsf[(4 * s4 + 0) * 68 + lane];
            float v01 = Vsf[(4 * s4 + 0) * 68 + lane + 32];
            float v10 = Vsf[(4 * s4 + 1) * 68 + lane];
            float v11 = Vsf[(4 * s4 + 1) * 68 + lane + 32];
            float v20 = Vsf[(4 * s4 + 2) * 68 + lane];
            float v21 = Vsf[(4 * s4 + 2) * 68 + lane + 32];
            float v30 = Vsf[(4 * s4 + 3) * 68 + lane];
            float v31 = Vsf[(4 * s4 + 3) * 68 + lane + 32];
            accA0 += pa.x * v00 + pa.y * v10 + pa.z * v20 + pa.w * v30;
            accA1 += pa.x * v01 + pa.y * v11 + pa.z * v21 + pa.w * v31;
            accB0 += pb.x * v00 + pb.y * v10 + pb.z * v20 + pb.w * v30;
            accB1 += pb.x * v01 + pb.y * v11 + pb.z * v21 + pb.w * v31;
        }
        __syncwarp();
    }

    int rowA = g_top[bh * NTOP + chunk * 8 + qa];
    int rowB = g_top[bh * NTOP + chunk * 8 + qb];
    float iA = 1.0f / lA, iB = 1.0f / lB;
    size_t oA = ((size_t)bh * L + rowA) * D;
    size_t oB = ((size_t)bh * L + rowB) * D;
    out[oA + lane]      = accA0 * iA;
    out[oA + lane + 32] = accA1 * iA;
    out[oB + lane]      = accB0 * iB;
    out[oB + lane + 32] = accB1 * iB;
}

// ---------------------------------------------------------------------------
extern "C" void kernel_launch(void* const* d_in, const int* in_sizes, int n_in,
                              void* d_out, int out_size) {
    const float* q = (const float*)d_in[0];
    const float* k = (const float*)d_in[1];
    const float* v = (const float*)d_in[2];
    float* out = (float*)d_out;

    gen_idx_kernel<<<(L * U + 255) / 256, 256>>>();
    compute_M_kernel<<<BH * (L / 16), 256>>>(q, k);
    topk_kernel<<<BH, 256>>>();
    sumv_part_kernel<<<BH * 8, 256>>>(v);
    sumv_reduce_kernel<<<BH, 64>>>();
    fill_kernel<<<(B * H * L * D / 4) / 256, 256>>>((float4*)out);
    attn_kernel<<<BH * 5, 128>>>(q, k, v, out);
}